// round 7
// baseline (speedup 1.0000x reference)
#include <cuda_runtime.h>
#include <math.h>
#include <stdint.h>

// Problem constants
#define B_    2
#define L_    13294
#define S_    13294
#define D_    256
#define NH_   8
#define HD_   32
#define M_    (B_ * L_)          // 26588 rows for all GEMMs

// Scratch (static device arrays — no allocation allowed)
__device__ float g_val   [(size_t)M_ * 256];  // value @ W_val    [B,S,NH,HD]
__device__ float g_offlog[(size_t)M_ * 384];  // query @ [W_off|W_attn]
__device__ float g_acc   [(size_t)M_ * 256];  // sampled output   [B,L,NH,HD]
__device__ float g_Wcat  [256 * 384];         // packed [W_off | W_attn]
__device__ float g_bcat  [384];               // packed [b_off | b_attn]

__device__ __forceinline__ uint32_t f2tf32(float f) {
    uint32_t u;
    asm("cvt.rna.tf32.f32 %0, %1;" : "=r"(u) : "f"(f));
    return u;
}

// ---------------------------------------------------------------------------
// Pack [W_off | W_attn] (K=256 rows) and biases into contiguous N=384 buffers.
// ---------------------------------------------------------------------------
__global__ void pack_qkw(const float* __restrict__ W_off,
                         const float* __restrict__ W_attn,
                         const float* __restrict__ b_off,
                         const float* __restrict__ b_attn,
                         float* __restrict__ Wcat, float* __restrict__ bcat) {
    const int i = blockIdx.x * blockDim.x + threadIdx.x;   // 256*384 threads
    const int k = i / 384;
    const int n = i % 384;
    Wcat[i] = (n < 256) ? W_off[k * 256 + n] : W_attn[k * 128 + (n - 256)];
    if (i < 384)
        bcat[i] = (i < 256) ? b_off[i] : b_attn[i - 256];
}

// ---------------------------------------------------------------------------
// tf32 tensor-core GEMM with bias: C[M,N] = A[M,K] @ W[K,N] + b[N]
// Block tile 128x128, BK=16, 256 threads = 8 warps, warp tile 64x32.
// Double-buffered smem: ONE __syncthreads per K-iteration.
// Requires K % 16 == 0, N % 128 == 0. M guarded.
// ---------------------------------------------------------------------------
__global__ __launch_bounds__(256, 2)
void gemm_tf32(const float* __restrict__ A, const float* __restrict__ W,
               const float* __restrict__ bias, float* __restrict__ C,
               int M, int N, int K) {
    __shared__ __align__(16) uint32_t As[2][128][20];
    __shared__ __align__(16) uint32_t Bs[2][16][132];

    const int t    = threadIdx.x;
    const int warp = t >> 5;
    const int lane = t & 31;
    const int g    = lane >> 2;
    const int tg   = lane & 3;
    const int wm   = (warp & 1) * 64;
    const int wn   = (warp >> 1) * 32;

    const int m0 = blockIdx.y * 128;
    const int n0 = blockIdx.x * 128;

    const int ar  = t >> 2;
    const int ak  = (t & 3) * 4;
    const int br  = t >> 5;
    const int bc  = (t & 31) * 4;

    float4 av0, av1, bv0, bv1;

    auto load_tiles = [&](int k0) {
        const float4 z = make_float4(0.f, 0.f, 0.f, 0.f);
        int r0 = m0 + ar;
        av0 = (r0 < M) ? *(const float4*)&A[(size_t)r0 * K + k0 + ak] : z;
        int r1 = r0 + 64;
        av1 = (r1 < M) ? *(const float4*)&A[(size_t)r1 * K + k0 + ak] : z;
        bv0 = *(const float4*)&W[(size_t)(k0 + br)     * N + n0 + bc];
        bv1 = *(const float4*)&W[(size_t)(k0 + br + 8) * N + n0 + bc];
    };
    auto store_tiles = [&](int buf) {
        uint4 u;
        u.x = f2tf32(av0.x); u.y = f2tf32(av0.y);
        u.z = f2tf32(av0.z); u.w = f2tf32(av0.w);
        *(uint4*)&As[buf][ar][ak] = u;
        u.x = f2tf32(av1.x); u.y = f2tf32(av1.y);
        u.z = f2tf32(av1.z); u.w = f2tf32(av1.w);
        *(uint4*)&As[buf][ar + 64][ak] = u;
        u.x = f2tf32(bv0.x); u.y = f2tf32(bv0.y);
        u.z = f2tf32(bv0.z); u.w = f2tf32(bv0.w);
        *(uint4*)&Bs[buf][br][bc] = u;
        u.x = f2tf32(bv1.x); u.y = f2tf32(bv1.y);
        u.z = f2tf32(bv1.z); u.w = f2tf32(bv1.w);
        *(uint4*)&Bs[buf][br + 8][bc] = u;
    };

    float acc[4][4][4];
#pragma unroll
    for (int i = 0; i < 4; i++)
#pragma unroll
        for (int j = 0; j < 4; j++)
#pragma unroll
            for (int r = 0; r < 4; r++) acc[i][j][r] = 0.f;

    const int niter = K / 16;
    load_tiles(0);
    store_tiles(0);
    __syncthreads();

    for (int it = 0; it < niter; ++it) {
        const int  buf  = it & 1;
        const bool more = (it + 1) < niter;
        if (more) load_tiles((it + 1) * 16);

#pragma unroll
        for (int ks = 0; ks < 2; ks++) {
            const int kb = ks * 8;
            uint32_t af[4][4], bf[4][2];
#pragma unroll
            for (int mt = 0; mt < 4; mt++) {
                const int r = wm + mt * 16 + g;
                af[mt][0] = As[buf][r    ][kb + tg];
                af[mt][1] = As[buf][r + 8][kb + tg];
                af[mt][2] = As[buf][r    ][kb + tg + 4];
                af[mt][3] = As[buf][r + 8][kb + tg + 4];
            }
#pragma unroll
            for (int nt = 0; nt < 4; nt++) {
                const int c = wn + nt * 8 + g;
                bf[nt][0] = Bs[buf][kb + tg    ][c];
                bf[nt][1] = Bs[buf][kb + tg + 4][c];
            }
#pragma unroll
            for (int mt = 0; mt < 4; mt++)
#pragma unroll
                for (int nt = 0; nt < 4; nt++) {
                    asm volatile(
                        "mma.sync.aligned.m16n8k8.row.col.f32.tf32.tf32.f32 "
                        "{%0,%1,%2,%3}, {%4,%5,%6,%7}, {%8,%9}, {%0,%1,%2,%3};"
                        : "+f"(acc[mt][nt][0]), "+f"(acc[mt][nt][1]),
                          "+f"(acc[mt][nt][2]), "+f"(acc[mt][nt][3])
                        : "r"(af[mt][0]), "r"(af[mt][1]),
                          "r"(af[mt][2]), "r"(af[mt][3]),
                          "r"(bf[nt][0]), "r"(bf[nt][1]));
                }
        }

        if (more) store_tiles(buf ^ 1);
        __syncthreads();
    }

    // Epilogue: bias add + store
#pragma unroll
    for (int nt = 0; nt < 4; nt++) {
        const int c = n0 + wn + nt * 8 + tg * 2;
        const float2 bb = *(const float2*)&bias[c];
#pragma unroll
        for (int mt = 0; mt < 4; mt++) {
            const int r0 = m0 + wm + mt * 16 + g;
            if (r0 < M) {
                float2 o = make_float2(acc[mt][nt][0] + bb.x,
                                       acc[mt][nt][1] + bb.y);
                *(float2*)&C[(size_t)r0 * N + c] = o;
            }
            const int r1 = r0 + 8;
            if (r1 < M) {
                float2 o = make_float2(acc[mt][nt][2] + bb.x,
                                       acc[mt][nt][3] + bb.y);
                *(float2*)&C[(size_t)r1 * N + c] = o;
            }
        }
    }
}

// ---------------------------------------------------------------------------
// Deformable sampling, 4-heads-per-warp. Reads offsets+logits from the fused
// [M,384] buffer (offsets at +0, logits at +256). min-blocks=5 to push
// occupancy from 4 to 5 blocks/SM (regs <= 51).
// ---------------------------------------------------------------------------
__global__ __launch_bounds__(256, 5)
void deform_sample4(const float* __restrict__ ref,     // [B,L,4,2]
                    const float* __restrict__ offlog,  // [B,L,384]
                    const float* __restrict__ val,     // [B,S,NH,HD]
                    float* __restrict__ acc_out) {     // [B,L,NH,HD]
    const int warp = blockIdx.x * 8 + (threadIdx.x >> 5);
    const int lane = threadIdx.x & 31;
    if (warp >= M_ * 2) return;

    const int bq = warp >> 1;
    const int b  = bq / L_;
    const int g  = lane >> 3;
    const int gl = lane & 7;
    const int h  = (warp & 1) * 4 + g;
    const int ch = gl * 4;

    const float* row = offlog + (size_t)bq * 384;

    // softmax over this head's 16 logits (2 per lane, 8 lanes/group)
    const float2 x2 = *(const float2*)(row + 256 + h * 16 + gl * 2);
    float m = fmaxf(x2.x, x2.y);
#pragma unroll
    for (int o = 1; o < 8; o <<= 1)
        m = fmaxf(m, __shfl_xor_sync(0xffffffffu, m, o));
    const float ex = expf(x2.x - m);
    const float ey = expf(x2.y - m);
    float ssum = ex + ey;
#pragma unroll
    for (int o = 1; o < 8; o <<= 1)
        ssum += __shfl_xor_sync(0xffffffffu, ssum, o);
    const float inv = 1.f / ssum;
    const float wnx = ex * inv;
    const float wny = ey * inv;

    const float4 off4 = *(const float4*)(row + h * 32 + gl * 4);

    const float* rp = ref + (size_t)bq * 8;
    const float4 r01 = *(const float4*)rp;
    const float4 r23 = *(const float4*)(rp + 4);
    const float rx_[4] = {r01.x, r01.z, r23.x, r23.z};
    const float ry_[4] = {r01.y, r01.w, r23.y, r23.w};

    const int HH[4] = {100, 50, 25, 13};
    const int ST[4] = {0, 10000, 12500, 13125};

    const float* vhead = val + (size_t)b * S_ * 256 + h * 32 + ch;

    float4 acc = make_float4(0.f, 0.f, 0.f, 0.f);
    const float4 z4 = make_float4(0.f, 0.f, 0.f, 0.f);

#pragma unroll
    for (int l = 0; l < 4; l++) {
        const int   Wd = HH[l];
        const float Wf = (float)Wd;
        const float rx = rx_[l];
        const float ry = ry_[l];
        const float* vrow = vhead + ST[l] * 256;

#pragma unroll
        for (int p = 0; p < 4; p++) {
            const int s   = l * 4 + p;
            const int src = s >> 1;
            float ox, oy, ws;
            if ((s & 1) == 0) {
                ox = __shfl_sync(0xffffffffu, off4.x, src, 8);
                oy = __shfl_sync(0xffffffffu, off4.y, src, 8);
                ws = __shfl_sync(0xffffffffu, wnx,   src, 8);
            } else {
                ox = __shfl_sync(0xffffffffu, off4.z, src, 8);
                oy = __shfl_sync(0xffffffffu, off4.w, src, 8);
                ws = __shfl_sync(0xffffffffu, wny,   src, 8);
            }

            const float xs = fmaf(rx, Wf, ox) - 0.5f;
            const float ys = fmaf(ry, Wf, oy) - 0.5f;
            const float x0f = floorf(xs);
            const float y0f = floorf(ys);
            const float fx = xs - x0f;
            const float fy = ys - y0f;
            const int x0 = (int)x0f;
            const int y0 = (int)y0f;

            const bool okx0 = (unsigned)x0       < (unsigned)Wd;
            const bool okx1 = (unsigned)(x0 + 1) < (unsigned)Wd;
            const bool oky0 = (unsigned)y0       < (unsigned)Wd;
            const bool oky1 = (unsigned)(y0 + 1) < (unsigned)Wd;

            const float gx0 = 1.f - fx;
            const float gy0 = 1.f - fy;
            const float u00 = ws * gx0 * gy0;
            const float u10 = ws * fx  * gy0;
            const float u01 = ws * gx0 * fy;
            const float u11 = ws * fx  * fy;

            const float* p00 = vrow + (y0 * Wd + x0) * 256;

            const float4 v00 = (okx0 && oky0) ? *(const float4*)(p00)                  : z4;
            const float4 v10 = (okx1 && oky0) ? *(const float4*)(p00 + 256)            : z4;
            const float4 v01 = (okx0 && oky1) ? *(const float4*)(p00 + Wd * 256)       : z4;
            const float4 v11 = (okx1 && oky1) ? *(const float4*)(p00 + Wd * 256 + 256) : z4;

            acc.x += u00 * v00.x + u10 * v10.x + u01 * v01.x + u11 * v11.x;
            acc.y += u00 * v00.y + u10 * v10.y + u01 * v01.y + u11 * v11.y;
            acc.z += u00 * v00.z + u10 * v10.z + u01 * v01.z + u11 * v11.z;
            acc.w += u00 * v00.w + u10 * v10.w + u01 * v01.w + u11 * v11.w;
        }
    }

    *(float4*)(acc_out + (size_t)bq * 256 + h * 32 + ch) = acc;
}

// ---------------------------------------------------------------------------
extern "C" void kernel_launch(void* const* d_in, const int* in_sizes, int n_in,
                              void* d_out, int out_size) {
    const float* query  = (const float*)d_in[0];
    const float* refpt  = (const float*)d_in[1];
    const float* value  = (const float*)d_in[2];
    const float* W_val  = (const float*)d_in[3];
    const float* b_val  = (const float*)d_in[4];
    const float* W_off  = (const float*)d_in[5];
    const float* b_off  = (const float*)d_in[6];
    const float* W_attn = (const float*)d_in[7];
    const float* b_attn = (const float*)d_in[8];
    const float* W_out  = (const float*)d_in[9];
    const float* b_out  = (const float*)d_in[10];
    float* out = (float*)d_out;

    float *val_s, *ol_s, *acc_s, *wc_s, *bc_s;
    cudaGetSymbolAddress((void**)&val_s, g_val);
    cudaGetSymbolAddress((void**)&ol_s,  g_offlog);
    cudaGetSymbolAddress((void**)&acc_s, g_acc);
    cudaGetSymbolAddress((void**)&wc_s,  g_Wcat);
    cudaGetSymbolAddress((void**)&bc_s,  g_bcat);

    const int M = M_;
    dim3 blk(256);
    dim3 gN256(2, (M + 127) / 128);
    dim3 gN384(3, (M + 127) / 128);

    // Pack fused query-projection weights (tiny)
    pack_qkw<<<(256 * 384) / 256, 256>>>(W_off, W_attn, b_off, b_attn, wc_s, bc_s);

    // Projections (tf32 tensor cores)
    gemm_tf32<<<gN256, blk>>>(value, W_val, b_val, val_s, M, 256, 256);
    gemm_tf32<<<gN384, blk>>>(query, wc_s, bc_s, ol_s, M, 384, 256);

    // Deformable sampling: one warp per (b,q, head-quad)
    const int warps = M_ * 2;
    deform_sample4<<<(warps + 7) / 8, 256>>>(refpt, ol_s, val_s, acc_s);

    // Output projection -> d_out (tf32 tensor cores)
    gemm_tf32<<<gN256, blk>>>(acc_s, W_out, b_out, out, M, 256, 256);
}